// round 1
// baseline (speedup 1.0000x reference)
#include <cuda_runtime.h>
#include <cuda_bf16.h>
#include <cstdint>

// Problem constants (fixed by the reference): N=1048576, F=64, C=128, B=4096.
#define TILE_M 128
#define F_DIM  64
#define C_DIM  128

// padded smem leading dims (bf16 elements). 72*2=144B (9 chunks), 136*2=272B (17 chunks):
// chunk index advances by odd count per row -> ldmatrix phases are bank-conflict-free.
#define AS_LD 72
#define BS_LD 136

__device__ __forceinline__ uint32_t pack_bf16(float lo, float hi) {
    uint32_t r;
    asm("cvt.rn.bf16x2.f32 %0, %1, %2;" : "=r"(r) : "f"(hi), "f"(lo));
    return r;
}

__global__ __launch_bounds__(256) void fused_mm_sigmoid_segsum(
    const float* __restrict__ x,     // [N, 64]
    const float* __restrict__ w,     // [64, 128]
    const int*   __restrict__ seg,   // [N] sorted
    float*       __restrict__ out)   // [B, 128], pre-zeroed
{
    __shared__ alignas(16) __nv_bfloat16 As[TILE_M * AS_LD];  // 18432 B
    __shared__ alignas(16) __nv_bfloat16 Bs[F_DIM * BS_LD];   // 17408 B

    const int tid  = threadIdx.x;
    const int warp = tid >> 5;
    const int lane = tid & 31;
    const long i0  = (long)blockIdx.x * TILE_M;

    // ---- Load x tile [128 x 64] fp32 -> bf16 smem (padded) ----
    const float4* x4 = reinterpret_cast<const float4*>(x) + i0 * (F_DIM / 4);
    #pragma unroll
    for (int it = 0; it < 8; it++) {
        int idx = tid + it * 256;            // 0..2047
        int r   = idx >> 4;                  // row 0..127
        int c4  = idx & 15;                  // float4 col 0..15
        float4 v = x4[idx];
        uint2 p;
        p.x = pack_bf16(v.x, v.y);
        p.y = pack_bf16(v.z, v.w);
        *reinterpret_cast<uint2*>(&As[r * AS_LD + c4 * 4]) = p;
    }
    // ---- Load w [64 x 128] fp32 -> bf16 smem (padded) ----
    const float4* w4 = reinterpret_cast<const float4*>(w);
    #pragma unroll
    for (int it = 0; it < 8; it++) {
        int idx = tid + it * 256;            // 0..2047
        int r   = idx >> 5;                  // row 0..63
        int c4  = idx & 31;                  // float4 col 0..31
        float4 v = w4[idx];
        uint2 p;
        p.x = pack_bf16(v.x, v.y);
        p.y = pack_bf16(v.z, v.w);
        *reinterpret_cast<uint2*>(&Bs[r * BS_LD + c4 * 4]) = p;
    }
    __syncthreads();

    // ---- GEMM: each warp computes rows [16*warp, 16*warp+16) x all 128 cols ----
    float acc[16][4];
    #pragma unroll
    for (int t = 0; t < 16; t++)
        #pragma unroll
        for (int j = 0; j < 4; j++) acc[t][j] = 0.0f;

    const int l15 = lane & 15;
    const int lh  = lane >> 4;
    uint32_t asBase = (uint32_t)__cvta_generic_to_shared(As);
    uint32_t bsBase = (uint32_t)__cvta_generic_to_shared(Bs);
    uint32_t aAddr  = asBase + (warp * 16 + l15) * (AS_LD * 2) + lh * 16; // row, k-half
    uint32_t bAddr  = bsBase + l15 * (BS_LD * 2);

    #pragma unroll
    for (int kk = 0; kk < 4; kk++) {
        uint32_t a0, a1, a2, a3;
        asm volatile(
            "ldmatrix.sync.aligned.m8n8.x4.shared.b16 {%0,%1,%2,%3}, [%4];"
            : "=r"(a0), "=r"(a1), "=r"(a2), "=r"(a3)
            : "r"(aAddr + kk * 32));
        uint32_t bk = bAddr + kk * 16 * (BS_LD * 2);
        #pragma unroll
        for (int t = 0; t < 16; t++) {
            uint32_t b0, b1;
            asm volatile(
                "ldmatrix.sync.aligned.m8n8.x2.trans.shared.b16 {%0,%1}, [%2];"
                : "=r"(b0), "=r"(b1)
                : "r"(bk + t * 16));
            asm volatile(
                "mma.sync.aligned.m16n8k16.row.col.f32.bf16.bf16.f32 "
                "{%0,%1,%2,%3}, {%4,%5,%6,%7}, {%8,%9}, {%0,%1,%2,%3};"
                : "+f"(acc[t][0]), "+f"(acc[t][1]), "+f"(acc[t][2]), "+f"(acc[t][3])
                : "r"(a0), "r"(a1), "r"(a2), "r"(a3), "r"(b0), "r"(b1));
        }
    }

    // ---- Sigmoid on fragments ----
    #pragma unroll
    for (int t = 0; t < 16; t++) {
        #pragma unroll
        for (int j = 0; j < 4; j++) {
            float v = acc[t][j];
            float e = __expf(-v);                    // EX2
            acc[t][j] = __fdividef(1.0f, 1.0f + e);  // RCP + MUL
        }
    }

    // ---- Segment reduction (segment_ids sorted globally) ----
    // Fragment layout: thread holds rows r0 = lane>>2 and r0+8 (within warp's 16 rows),
    // cols c = 8t + 2*(lane&3), c+1. acc[t] = {r0c, r0c+1, r8c, r8c+1}.
    const int g0 = (int)i0 + warp * 16;
    const int q  = lane >> 2;
    const int segFirst = seg[g0];
    const int segLast  = seg[g0 + 15];

    if (segFirst == segLast) {
        // fast path: all 16 rows in one bag -> butterfly reduce over rows, 8 REDs/tile
        #pragma unroll
        for (int t = 0; t < 16; t++) {
            float v0 = acc[t][0] + acc[t][2];
            float v1 = acc[t][1] + acc[t][3];
            #pragma unroll
            for (int d = 4; d < 32; d <<= 1) {
                v0 += __shfl_xor_sync(0xffffffffu, v0, d);
                v1 += __shfl_xor_sync(0xffffffffu, v1, d);
            }
            if (lane < 4) {
                int c = t * 8 + (lane & 3) * 2;
                atomicAdd(&out[(long)segFirst * C_DIM + c],     v0);
                atomicAdd(&out[(long)segFirst * C_DIM + c + 1], v1);
            }
        }
    } else {
        // boundary warp (~6% of warps): per-element global REDs
        const int s0 = seg[g0 + q];
        const int s1 = seg[g0 + q + 8];
        #pragma unroll
        for (int t = 0; t < 16; t++) {
            int c = t * 8 + (lane & 3) * 2;
            atomicAdd(&out[(long)s0 * C_DIM + c],     acc[t][0]);
            atomicAdd(&out[(long)s0 * C_DIM + c + 1], acc[t][1]);
            atomicAdd(&out[(long)s1 * C_DIM + c],     acc[t][2]);
            atomicAdd(&out[(long)s1 * C_DIM + c + 1], acc[t][3]);
        }
    }
}

extern "C" void kernel_launch(void* const* d_in, const int* in_sizes, int n_in,
                              void* d_out, int out_size) {
    const float* x   = (const float*)d_in[0];
    const float* w   = (const float*)d_in[1];
    const int*   seg = (const int*)d_in[2];
    float*       out = (float*)d_out;

    // d_out is poisoned -> zero it (graph-capturable, no allocations)
    cudaMemsetAsync(d_out, 0, (size_t)out_size * sizeof(float), 0);

    int n    = in_sizes[0] / F_DIM;   // N = 1048576
    int grid = n / TILE_M;            // 8192 blocks
    fused_mm_sigmoid_segsum<<<grid, 256>>>(x, w, seg, out);
}